// round 8
// baseline (speedup 1.0000x reference)
#include <cuda_runtime.h>
#include <cuda_bf16.h>
#include <cuda_fp16.h>
#include <math.h>
#include <stdint.h>

#define NB 32
#define NS 96
#define NH 512
#define G4H 2048
#define NV 32000

// ---------------- float scratch offsets ----------------
#define OFF_EMBS 0u
#define OFF_EMBT (OFF_EMBS + 786432u)
#define OFF_XPA  (OFF_EMBT + 786432u)
#define OFF_XPB  (OFF_XPA + 6291456u)
#define OFF_ENCO (OFF_XPB + 6291456u)
#define OFF_COMB (OFF_ENCO + 1572864u)
#define OFF_HT   (OFF_COMB + 3145728u)
#define OFF_CT   (OFF_HT + 65536u)
#define OFF_DH0  (OFF_CT + 65536u)
#define OFF_DC0  (OFF_DH0 + 32768u)
#define OFF_HBUF (OFF_DC0 + 32768u)
#define OFF_ZERO (OFF_HBUF + 65536u)
#define OFF_DSCR (OFF_ZERO + 16384u)
#define OFF_POOL (OFF_DSCR + 65536u)
// ---------------- 16-bit pool offsets (elements) ----------------
#define PB_FCWH 0u
#define PB_FCWL 32768000u
#define PB_W    65536000u
#define PB_EW0FH (PB_W + 0u)
#define PB_EW0FL (PB_W + 524288u)
#define PB_EW0BH (PB_W + 1048576u)
#define PB_EW0BL (PB_W + 1572864u)
#define PB_EW1FH (PB_W + 2097152u)
#define PB_EW1FL (PB_W + 4194304u)
#define PB_EW1BH (PB_W + 6291456u)
#define PB_EW1BL (PB_W + 8388608u)
#define PB_DW0H  (PB_W + 10485760u)
#define PB_DW0L  (PB_W + 11010048u)
#define PB_DW1H  (PB_W + 11534336u)
#define PB_DW1L  (PB_W + 12582912u)
#define PB_OWH   (PB_W + 13631488u)
#define PB_OWL   (PB_W + 14155776u)
#define PB_ACTH  80216064u
#define PB_ACTL  83361792u
#define PB_EMBSH 86507520u
#define PB_EMBSL 87293952u
#define PB_EMBTH 88080384u
#define PB_EMBTL 88866816u
#define POOL_BF16 89653248u

#define TOTALF (OFF_POOL + (POOL_BF16 + 1u) / 2u + 64u)

__device__ __align__(128) float g_buf[TOTALF];
__device__ unsigned g_barrier[8];

// =================== helpers ===================
__device__ __forceinline__ uint32_t smem_to_u32(const void* p) {
    uint32_t a;
    asm("{ .reg .u64 t; cvta.to.shared.u64 t, %1; cvt.u32.u64 %0, t; }" : "=r"(a) : "l"(p));
    return a;
}
#define CP16(dst, src) asm volatile( \
    "cp.async.cg.shared.global [%0], [%1], 16;" :: "r"(dst), "l"(src))
#define CP_COMMIT() asm volatile("cp.async.commit_group;")
#define CP_WAIT1() asm volatile("cp.async.wait_group 1;")

__device__ __forceinline__ void mma_bf16(float* c, const uint32_t* a, const uint32_t* b) {
    asm volatile(
        "mma.sync.aligned.m16n8k16.row.col.f32.bf16.bf16.f32 "
        "{%0,%1,%2,%3}, {%4,%5,%6,%7}, {%8,%9}, {%0,%1,%2,%3};"
        : "+f"(c[0]), "+f"(c[1]), "+f"(c[2]), "+f"(c[3])
        : "r"(a[0]), "r"(a[1]), "r"(a[2]), "r"(a[3]), "r"(b[0]), "r"(b[1]));
}
__device__ __forceinline__ void mma_f16(float* c, const uint32_t* a, const uint32_t* b) {
    asm volatile(
        "mma.sync.aligned.m16n8k16.row.col.f32.f16.f16.f32 "
        "{%0,%1,%2,%3}, {%4,%5,%6,%7}, {%8,%9}, {%0,%1,%2,%3};"
        : "+f"(c[0]), "+f"(c[1]), "+f"(c[2]), "+f"(c[3])
        : "r"(a[0]), "r"(a[1]), "r"(a[2]), "r"(a[3]), "r"(b[0]), "r"(b[1]));
}

// ---------------- embedding gather ----------------
__global__ void embed_kernel(const int* __restrict__ seq, const float* __restrict__ emb,
                             float* __restrict__ out) {
    int tok = blockIdx.x;
    int id = seq[tok];
    const float4* s = (const float4*)(emb + (size_t)id * 256);
    float4* d = (float4*)(out + (size_t)tok * 256);
    d[threadIdx.x] = s[threadIdx.x];
}

// ---------------- fp32 -> bf16 hi/lo (4-way ILP) ----------------
__device__ __forceinline__ void bf_split1(float4 v, __nv_bfloat162* H, __nv_bfloat162* L,
                                          int i) {
    __nv_bfloat16 h0 = __float2bfloat16(v.x), h1 = __float2bfloat16(v.y);
    __nv_bfloat16 h2 = __float2bfloat16(v.z), h3 = __float2bfloat16(v.w);
    H[i * 2] = __nv_bfloat162(h0, h1);
    H[i * 2 + 1] = __nv_bfloat162(h2, h3);
    L[i * 2] = __nv_bfloat162(__float2bfloat16(v.x - __bfloat162float(h0)),
                              __float2bfloat16(v.y - __bfloat162float(h1)));
    L[i * 2 + 1] = __nv_bfloat162(__float2bfloat16(v.z - __bfloat162float(h2)),
                                  __float2bfloat16(v.w - __bfloat162float(h3)));
}

__global__ void split_kernel(const float* __restrict__ in, __nv_bfloat16* __restrict__ hi,
                             __nv_bfloat16* __restrict__ lo, int n4) {
    int tot = gridDim.x * 256;
    __nv_bfloat162* H = (__nv_bfloat162*)hi;
    __nv_bfloat162* L = (__nv_bfloat162*)lo;
    for (int t = blockIdx.x * 256 + threadIdx.x; t < n4; t += 4 * tot) {
        int i1 = t + tot, i2 = t + 2 * tot, i3 = t + 3 * tot;
        float4 v0 = ((const float4*)in)[t];
        float4 v1, v2, v3;
        if (i1 < n4) v1 = ((const float4*)in)[i1];
        if (i2 < n4) v2 = ((const float4*)in)[i2];
        if (i3 < n4) v3 = ((const float4*)in)[i3];
        bf_split1(v0, H, L, t);
        if (i1 < n4) bf_split1(v1, H, L, i1);
        if (i2 < n4) bf_split1(v2, H, L, i2);
        if (i3 < n4) bf_split1(v3, H, L, i3);
    }
}

// ---------------- fp32 -> fp16 hi/lo with pre-scale ----------------
__device__ __forceinline__ void f16_split1(float4 v, __half2* H, __half2* L, int i,
                                           float scale) {
    float x0 = v.x * scale, x1 = v.y * scale, x2 = v.z * scale, x3 = v.w * scale;
    __half h0 = __float2half_rn(x0), h1 = __float2half_rn(x1);
    __half h2 = __float2half_rn(x2), h3 = __float2half_rn(x3);
    H[i * 2] = __half2(h0, h1);
    H[i * 2 + 1] = __half2(h2, h3);
    L[i * 2] = __half2(__float2half_rn(x0 - __half2float(h0)),
                       __float2half_rn(x1 - __half2float(h1)));
    L[i * 2 + 1] = __half2(__float2half_rn(x2 - __half2float(h2)),
                           __float2half_rn(x3 - __half2float(h3)));
}

__global__ void split16_pair_kernel(const float* __restrict__ in, __half* __restrict__ hi,
                                    __half* __restrict__ lo, int n4, float scale) {
    int tot = gridDim.x * 256;
    __half2* H = (__half2*)hi;
    __half2* L = (__half2*)lo;
    for (int t = blockIdx.x * 256 + threadIdx.x; t < n4; t += 4 * tot) {
        int i1 = t + tot, i2 = t + 2 * tot, i3 = t + 3 * tot;
        float4 v0 = ((const float4*)in)[t];
        float4 v1, v2, v3;
        if (i1 < n4) v1 = ((const float4*)in)[i1];
        if (i2 < n4) v2 = ((const float4*)in)[i2];
        if (i3 < n4) v3 = ((const float4*)in)[i3];
        f16_split1(v0, H, L, t, scale);
        if (i1 < n4) f16_split1(v1, H, L, i1, scale);
        if (i2 < n4) f16_split1(v2, H, L, i2, scale);
        if (i3 < n4) f16_split1(v3, H, L, i3, scale);
    }
}

// ---------------- small fp32 SGEMM (bridge only) ----------------
__global__ void __launch_bounds__(256) sgemm_kernel(
    const float* __restrict__ A, const float* __restrict__ Bw,
    const float* __restrict__ bias, float* __restrict__ C, int M, int N, int K) {
    __shared__ __align__(16) float As[8][128];
    __shared__ __align__(16) float Bs[8][128];
    int tid = threadIdx.x;
    int bn = blockIdx.x, bm = blockIdx.y;
    int row = tid >> 1, kq = (tid & 1) * 4;
    int gm = bm * 128 + row, gn = bn * 128 + row;
    int tx = tid & 15, ty = tid >> 4;
    bool am = gm < M, bok = gn < N;
    const float* Ap = A + (size_t)gm * K + kq;
    const float* Bp = Bw + (size_t)gn * K + kq;
    float acc[8][8];
#pragma unroll
    for (int i = 0; i < 8; i++)
#pragma unroll
        for (int j = 0; j < 8; j++) acc[i][j] = 0.f;
    for (int k0 = 0; k0 < K; k0 += 8) {
        float4 av = am ? *(const float4*)(Ap + k0) : make_float4(0, 0, 0, 0);
        float4 bv = bok ? *(const float4*)(Bp + k0) : make_float4(0, 0, 0, 0);
        __syncthreads();
        As[kq + 0][row] = av.x; As[kq + 1][row] = av.y;
        As[kq + 2][row] = av.z; As[kq + 3][row] = av.w;
        Bs[kq + 0][row] = bv.x; Bs[kq + 1][row] = bv.y;
        Bs[kq + 2][row] = bv.z; Bs[kq + 3][row] = bv.w;
        __syncthreads();
#pragma unroll
        for (int kk = 0; kk < 8; kk++) {
            float4 a0 = *(const float4*)&As[kk][ty * 8];
            float4 a1 = *(const float4*)&As[kk][ty * 8 + 4];
            float4 b0 = *(const float4*)&Bs[kk][tx * 8];
            float4 b1 = *(const float4*)&Bs[kk][tx * 8 + 4];
            float a[8] = {a0.x, a0.y, a0.z, a0.w, a1.x, a1.y, a1.z, a1.w};
            float b[8] = {b0.x, b0.y, b0.z, b0.w, b1.x, b1.y, b1.z, b1.w};
#pragma unroll
            for (int i = 0; i < 8; i++)
#pragma unroll
                for (int j = 0; j < 8; j++) acc[i][j] = fmaf(a[i], b[j], acc[i][j]);
        }
    }
#pragma unroll
    for (int i = 0; i < 8; i++) {
        int m = bm * 128 + ty * 8 + i;
        if (m >= M) continue;
#pragma unroll
        for (int j = 0; j < 8; j++) {
            int n = bn * 128 + tx * 8 + j;
            if (n < N) C[(size_t)m * N + n] = acc[i][j] + bias[n];
        }
    }
}

// ---------------- bf16 3-product GEMM (A hi/lo, B hi/lo) ----------------
#define PLB 10240
#define STB (4 * PLB)
#define GEMM3_SMEM (2 * STB)

__device__ __forceinline__ void issue_stage4(
    uint32_t d, const __nv_bfloat16* a0, const __nv_bfloat16* a1,
    const __nv_bfloat16* b0, const __nv_bfloat16* b1) {
    CP16(d, a0);                 CP16(d + 16, a0 + 8);
    CP16(d + PLB, a1);           CP16(d + PLB + 16, a1 + 8);
    CP16(d + 2 * PLB, b0);       CP16(d + 2 * PLB + 16, b0 + 8);
    CP16(d + 3 * PLB, b1);       CP16(d + 3 * PLB + 16, b1 + 8);
}

__global__ void __launch_bounds__(256, 2) gemm_mma_kernel(
    const __nv_bfloat16* __restrict__ Ah, const __nv_bfloat16* __restrict__ Al,
    const __nv_bfloat16* __restrict__ Bh, const __nv_bfloat16* __restrict__ Bl,
    const float* __restrict__ bias, float* __restrict__ C, int M, int N, int K) {
    extern __shared__ __align__(16) char smraw[];
    uint32_t sb = smem_to_u32(smraw);
    const uint32_t* sw = (const uint32_t*)smraw;
    int tid = threadIdx.x;
    int wid = tid >> 5, lane = tid & 31;
    int m0 = blockIdx.x * 128, n0 = blockIdx.y * 128;
    int wm = (wid >> 2) * 64, wn = (wid & 3) * 32;
    int tp = lane >> 2, tq = lane & 3;

    int row = tid >> 1;
    int cpair = (tid & 1) * 2;
    const __nv_bfloat16* gA0 = Ah + (size_t)(m0 + row) * K + cpair * 8;
    const __nv_bfloat16* gA1 = Al + (size_t)(m0 + row) * K + cpair * 8;
    const __nv_bfloat16* gB0 = Bh + (size_t)(n0 + row) * K + cpair * 8;
    const __nv_bfloat16* gB1 = Bl + (size_t)(n0 + row) * K + cpair * 8;
    uint32_t dthr = sb + row * 80 + cpair * 16;

    float acc[4][4][4];
#pragma unroll
    for (int mt = 0; mt < 4; mt++)
#pragma unroll
        for (int nt = 0; nt < 4; nt++)
#pragma unroll
            for (int q = 0; q < 4; q++) acc[mt][nt][q] = 0.f;

    int nst = K / 32;
    issue_stage4(dthr, gA0, gA1, gB0, gB1);
    CP_COMMIT();
    for (int s = 0; s < nst; s++) {
        if (s + 1 < nst) {
            int k0 = (s + 1) * 32;
            issue_stage4(dthr + ((s + 1) & 1) * STB, gA0 + k0, gA1 + k0, gB0 + k0, gB1 + k0);
        }
        CP_COMMIT();
        CP_WAIT1();
        __syncthreads();
        int base = ((s & 1) * STB) >> 2;
#pragma unroll
        for (int kk = 0; kk < 2; kk++) {
            uint32_t bfr[2][4][2];
#pragma unroll
            for (int p = 0; p < 2; p++)
#pragma unroll
                for (int nt = 0; nt < 4; nt++) {
                    int r = wn + nt * 8 + tp;
                    int w0 = base + 5120 + p * 2560 + r * 20 + kk * 8 + tq;
                    bfr[p][nt][0] = sw[w0];
                    bfr[p][nt][1] = sw[w0 + 4];
                }
            uint32_t af[4][4];
#pragma unroll
            for (int mt = 0; mt < 4; mt++) {
                int r = wm + mt * 16 + tp;
                int w0 = base + r * 20 + kk * 8 + tq;
                af[mt][0] = sw[w0]; af[mt][1] = sw[w0 + 160];
                af[mt][2] = sw[w0 + 4]; af[mt][3] = sw[w0 + 164];
            }
#pragma unroll
            for (int mt = 0; mt < 4; mt++)
#pragma unroll
                for (int nt = 0; nt < 4; nt++) {
                    mma_bf16(acc[mt][nt], af[mt], bfr[0][nt]);
                    mma_bf16(acc[mt][nt], af[mt], bfr[1][nt]);
                }
#pragma unroll
            for (int mt = 0; mt < 4; mt++) {
                int r = wm + mt * 16 + tp;
                int w0 = base + 2560 + r * 20 + kk * 8 + tq;
                af[mt][0] = sw[w0]; af[mt][1] = sw[w0 + 160];
                af[mt][2] = sw[w0 + 4]; af[mt][3] = sw[w0 + 164];
            }
#pragma unroll
            for (int mt = 0; mt < 4; mt++)
#pragma unroll
                for (int nt = 0; nt < 4; nt++)
                    mma_bf16(acc[mt][nt], af[mt], bfr[0][nt]);
        }
        __syncthreads();
    }
#pragma unroll
    for (int mt = 0; mt < 4; mt++) {
        int r = m0 + wm + mt * 16 + tp;
#pragma unroll
        for (int nt = 0; nt < 4; nt++) {
            int c = n0 + wn + nt * 8 + tq * 2;
            float b0v = bias[c], b1v = bias[c + 1];
            *(float2*)&C[(size_t)r * N + c] =
                make_float2(acc[mt][nt][0] + b0v, acc[mt][nt][1] + b1v);
            *(float2*)&C[(size_t)(r + 8) * N + c] =
                make_float2(acc[mt][nt][2] + b0v, acc[mt][nt][3] + b1v);
        }
    }
}

// ---------------- fp16 2-product GEMM (A single, B hi/lo, C scaled) ----------------
#define PLB2 10240
#define STB2 (3 * PLB2)
#define GEMM2_SMEM (2 * STB2)

__global__ void __launch_bounds__(256, 2) gemm_f16_kernel(
    const __half* __restrict__ Aa, const __half* __restrict__ Bh,
    const __half* __restrict__ Bl, const float* __restrict__ bias,
    float* __restrict__ C, int M, int N, int K, float outScale) {
    extern __shared__ __align__(16) char smraw[];
    uint32_t sb = smem_to_u32(smraw);
    const uint32_t* sw = (const uint32_t*)smraw;
    int tid = threadIdx.x;
    int wid = tid >> 5, lane = tid & 31;
    int m0 = blockIdx.x * 128, n0 = blockIdx.y * 128;
    int wm = (wid >> 2) * 64, wn = (wid & 3) * 32;
    int tp = lane >> 2, tq = lane & 3;

    int row = tid >> 1;
    int cpair = (tid & 1) * 2;
    const __half* gA = Aa + (size_t)(m0 + row) * K + cpair * 8;
    const __half* gB0 = Bh + (size_t)(n0 + row) * K + cpair * 8;
    const __half* gB1 = Bl + (size_t)(n0 + row) * K + cpair * 8;
    uint32_t dthr = sb + row * 80 + cpair * 16;

    float acc[4][4][4];
#pragma unroll
    for (int mt = 0; mt < 4; mt++)
#pragma unroll
        for (int nt = 0; nt < 4; nt++)
#pragma unroll
            for (int q = 0; q < 4; q++) acc[mt][nt][q] = 0.f;

    int nst = K / 32;
    {
        CP16(dthr, gA); CP16(dthr + 16, gA + 8);
        CP16(dthr + PLB2, gB0); CP16(dthr + PLB2 + 16, gB0 + 8);
        CP16(dthr + 2 * PLB2, gB1); CP16(dthr + 2 * PLB2 + 16, gB1 + 8);
    }
    CP_COMMIT();
    for (int s = 0; s < nst; s++) {
        if (s + 1 < nst) {
            int k0 = (s + 1) * 32;
            uint32_t d = dthr + ((s + 1) & 1) * STB2;
            CP16(d, gA + k0); CP16(d + 16, gA + k0 + 8);
            CP16(d + PLB2, gB0 + k0); CP16(d + PLB2 + 16, gB0 + k0 + 8);
            CP16(d + 2 * PLB2, gB1 + k0); CP16(d + 2 * PLB2 + 16, gB1 + k0 + 8);
        }
        CP_COMMIT();
        CP_WAIT1();
        __syncthreads();
        int base = ((s & 1) * STB2) >> 2;
#pragma unroll
        for (int kk = 0; kk < 2; kk++) {
            uint32_t bfr[2][4][2];
#pragma unroll
            for (int p = 0; p < 2; p++)
#pragma unroll
                for (int nt = 0; nt < 4; nt++) {
                    int r = wn + nt * 8 + tp;
                    int w0 = base + 2560 + p * 2560 + r * 20 + kk * 8 + tq;
                    bfr[p][nt][0] = sw[w0];
                    bfr[p][nt][1] = sw[w0 + 4];
                }
            uint32_t af[4][4];
#pragma unroll
            for (int mt = 0; mt < 4; mt++) {
                int r = wm + mt * 16 + tp;
                int w0 = base + r * 20 + kk * 8 + tq;
                af[mt][0] = sw[w0]; af[mt][1] = sw[w0 + 160];
                af[mt][2] = sw[w0 + 4]; af[mt][3] = sw[w0 + 164];
            }
#pragma unroll
            for (int mt = 0; mt < 4; mt++)
#pragma unroll
                for (int nt = 0; nt < 4; nt++) {
                    mma_f16(acc[mt][nt], af[mt], bfr[0][nt]);
                    mma_f16(acc[mt][nt], af[mt], bfr[1][nt]);
                }
        }
        __syncthreads();
    }
#pragma unroll
    for (int mt = 0; mt < 4; mt++) {
        int r = m0 + wm + mt * 16 + tp;
#pragma unroll
        for (int nt = 0; nt < 4; nt++) {
            int c = n0 + wn + nt * 8 + tq * 2;
            float b0v = bias[c], b1v = bias[c + 1];
            *(float2*)&C[(size_t)r * N + c] =
                make_float2(acc[mt][nt][0] * outScale + b0v, acc[mt][nt][1] * outScale + b1v);
            *(float2*)&C[(size_t)(r + 8) * N + c] =
                make_float2(acc[mt][nt][2] * outScale + b0v, acc[mt][nt][3] * outScale + b1v);
        }
    }
}

// ---------------- persistent LSTM scan (fmaf, fused 16-bit outputs) ----------------
struct ScanArgs {
    const float* xp;
    const float* U;
    const float* h_init;
    const float* c_init;
    float* hb0; float* hb1;
    float* hs;                 // fp32 output (nullable), col-pre-offset
    __nv_bfloat16* hsH;        // bf16 hi plane (nullable), col-pre-offset
    __nv_bfloat16* hsL;        // bf16 lo plane
    __half* hsF16;             // fp16 plane (nullable)
    float* hT; float* cT;
    int reverse; int hsStride;
};

__device__ __forceinline__ float sigm(float x) { return 1.f / (1.f + expf(-x)); }

#define HCB 4
#define SPITCH 532
#define KHALF 272
#define SMEM_SCAN ((16 + 32) * SPITCH * 4)

__global__ void __launch_bounds__(256) scan_kernel(ScanArgs A0, ScanArgs A1, int nDir,
                                                   unsigned* bar) {
    extern __shared__ float sm[];
    int bpd = gridDim.x / nDir;
    int dir = blockIdx.x / bpd;
    ScanArgs a = dir ? A1 : A0;
    unsigned* mybar = bar + dir;
    int hc0 = (blockIdx.x % bpd) * HCB;
    int tid = threadIdx.x;
    float* sW = sm;                    // [16][SPITCH]
    float* sh = sm + 16 * SPITCH;      // [32][SPITCH]
    for (int i = tid; i < 16 * 128; i += 256) {
        int r = i >> 7, k4 = (i & 127) * 4;
        int kst = k4 + (k4 >= 256 ? (KHALF - 256) : 0);
        int gg = r >> 2, hc = r & 3;
        *(float4*)&sW[r * SPITCH + kst] =
            *(const float4*)(a.U + ((size_t)(gg * 512 + hc0 + hc)) * 512 + k4);
    }
    int b = tid >> 3;
    int sub = (tid >> 2) & 1;
    int hc = tid & 3;
    int kbo = sub * KHALF;
    float creg = a.c_init[b * 512 + hc0 + hc];
    const float* w_i = &sW[(0 * HCB + hc) * SPITCH + kbo];
    const float* w_f = &sW[(1 * HCB + hc) * SPITCH + kbo];
    const float* w_g = &sW[(2 * HCB + hc) * SPITCH + kbo];
    const float* w_o = &sW[(3 * HCB + hc) * SPITCH + kbo];

    for (int t = 0; t < 96; t++) {
        const float* hsrc = (t == 0) ? a.h_init : ((t & 1) ? a.hb1 : a.hb0);
        __syncthreads();
        for (int i = tid; i < 32 * 128; i += 256) {
            int bb = i >> 7, k4 = (i & 127) * 4;
            int kst = k4 + (k4 >= 256 ? (KHALF - 256) : 0);
            float4 v = __ldcv((const float4*)(hsrc + bb * 512 + k4));
            *(float4*)&sh[bb * SPITCH + kst] = v;
        }
        __syncthreads();
        float ai = 0, af = 0, ag = 0, ao = 0;
        const float* hrow = &sh[b * SPITCH + kbo];
#pragma unroll 4
        for (int k = 0; k < 256; k += 4) {
            float4 hv = *(const float4*)&hrow[k];
            float4 wi = *(const float4*)&w_i[k];
            float4 wf = *(const float4*)&w_f[k];
            float4 wg = *(const float4*)&w_g[k];
            float4 wo = *(const float4*)&w_o[k];
            ai = fmaf(hv.x, wi.x, ai); ai = fmaf(hv.y, wi.y, ai);
            ai = fmaf(hv.z, wi.z, ai); ai = fmaf(hv.w, wi.w, ai);
            af = fmaf(hv.x, wf.x, af); af = fmaf(hv.y, wf.y, af);
            af = fmaf(hv.z, wf.z, af); af = fmaf(hv.w, wf.w, af);
            ag = fmaf(hv.x, wg.x, ag); ag = fmaf(hv.y, wg.y, ag);
            ag = fmaf(hv.z, wg.z, ag); ag = fmaf(hv.w, wg.w, ag);
            ao = fmaf(hv.x, wo.x, ao); ao = fmaf(hv.y, wo.y, ao);
            ao = fmaf(hv.z, wo.z, ao); ao = fmaf(hv.w, wo.w, ao);
        }
        ai += __shfl_xor_sync(~0u, ai, 4);
        af += __shfl_xor_sync(~0u, af, 4);
        ag += __shfl_xor_sync(~0u, ag, 4);
        ao += __shfl_xor_sync(~0u, ao, 4);
        if (sub == 0) {
            int tsrc = a.reverse ? 95 - t : t;
            const float* xr = a.xp + ((size_t)(b * 96 + tsrc)) * 2048 + hc0 + hc;
            float gi = ai + xr[0], gf = af + xr[512];
            float gg2 = ag + xr[1024], go = ao + xr[1536];
            creg = sigm(gf) * creg + sigm(gi) * tanhf(gg2);
            float hn = sigm(go) * tanhf(creg);
            float* hdst = (t & 1) ? a.hb0 : a.hb1;
            hdst[b * 512 + hc0 + hc] = hn;
            int orow = (b * 96 + tsrc) * a.hsStride + hc0 + hc;
            if (a.hs) a.hs[orow] = hn;
            if (a.hsH) {
                __nv_bfloat16 hh = __float2bfloat16(hn);
                a.hsH[orow] = hh;
                a.hsL[orow] = __float2bfloat16(hn - __bfloat162float(hh));
            }
            if (a.hsF16) a.hsF16[orow] = __float2half_rn(hn);
            if (t == 95) {
                a.hT[b * 1024 + hc0 + hc] = hn;
                a.cT[b * 1024 + hc0 + hc] = creg;
            }
        }
        if (t < 95) {
            __threadfence();
            __syncthreads();
            if (tid == 0) {
                atomicAdd(mybar, 1u);
                unsigned target = (unsigned)bpd * (unsigned)(t + 1);
                while (*((volatile unsigned*)mybar) < target) { }
                __threadfence();
            }
            __syncthreads();
        }
    }
}

// ---------------- fused attention (writes fp32 + fp16 ctx) ----------------
#define ATT_SE 0
#define ATT_SY (96 * 513)
#define ATT_AT (ATT_SY + 512)
#define ATT_MK (ATT_AT + 96)
#define ATT_RD (ATT_MK + 96)
#define SMEM_ATT ((ATT_RD + 2) * 4)

__global__ void __launch_bounds__(128) attention_kernel(
    const float* __restrict__ encout, const int* __restrict__ src,
    float* __restrict__ comb, __half* __restrict__ combF16) {
    extern __shared__ float sh[];
    float* se = sh + ATT_SE;
    float* sy = sh + ATT_SY;
    float* sAttn = sh + ATT_AT;
    float* sMask = sh + ATT_MK;
    float* sRed = sh + ATT_RD;
    int b = blockIdx.x, tchunk = blockIdx.y, tid = threadIdx.x;
    for (int i = tid; i < 96 * 128; i += 128) {
        int r = i >> 7, c4 = (i & 127) << 2;
        float4 v = *(const float4*)(encout + ((size_t)(b * NS + r)) * NH + c4);
        float* d = se + r * 513 + c4;
        d[0] = v.x; d[1] = v.y; d[2] = v.z; d[3] = v.w;
    }
    if (tid < 96) sMask[tid] = (src[b * NS + tid] != 0) ? 1.f : 0.f;
    __syncthreads();
    for (int tt = 0; tt < 8; tt++) {
        int t = tchunk * 8 + tt;
        ((float4*)sy)[tid] = *(const float4*)(comb + ((size_t)(b * NS + t)) * 1024 + tid * 4);
        __syncthreads();
        if (tid < 96) {
            float e = 0.f;
            const float* r = se + tid * 513;
#pragma unroll 8
            for (int k = 0; k < NH; k++) e = fmaf(sy[k], r[k], e);
            sAttn[tid] = (sMask[tid] != 0.f) ? e : -1e10f;
        }
        __syncthreads();
        if (tid < 32) {
            float m = fmaxf(sAttn[tid], fmaxf(sAttn[tid + 32], sAttn[tid + 64]));
            for (int o = 16; o > 0; o >>= 1) m = fmaxf(m, __shfl_xor_sync(~0u, m, o));
            if (tid == 0) sRed[0] = m;
        }
        __syncthreads();
        if (tid < 96) sAttn[tid] = expf(sAttn[tid] - sRed[0]);
        __syncthreads();
        if (tid < 32) {
            float sv = sAttn[tid] + sAttn[tid + 32] + sAttn[tid + 64];
            for (int o = 16; o > 0; o >>= 1) sv += __shfl_xor_sync(~0u, sv, o);
            if (tid == 0) sRed[1] = sv;
        }
        __syncthreads();
        float inv = 1.f / sRed[1];
        float a0 = 0, a1 = 0, a2 = 0, a3 = 0;
        for (int s = 0; s < 96; s++) {
            float w = sAttn[s];
            const float* r = se + s * 513;
            a0 = fmaf(w, r[tid], a0);
            a1 = fmaf(w, r[tid + 128], a1);
            a2 = fmaf(w, r[tid + 256], a2);
            a3 = fmaf(w, r[tid + 384], a3);
        }
        a0 *= inv; a1 *= inv; a2 *= inv; a3 *= inv;
        size_t rb = ((size_t)(b * NS + t)) * 1024 + 512;
        float* o = comb + rb;
        o[tid] = a0; o[tid + 128] = a1; o[tid + 256] = a2; o[tid + 384] = a3;
        __half* of = combF16 + rb;
        of[tid] = __float2half_rn(a0);
        of[tid + 128] = __float2half_rn(a1);
        of[tid + 256] = __float2half_rn(a2);
        of[tid + 384] = __float2half_rn(a3);
        __syncthreads();
    }
}

// ---------------- host ----------------
#define SPG(n4) (((n4) + 1023) / 1024)

extern "C" void kernel_launch(void* const* d_in, const int* in_sizes, int n_in,
                              void* d_out, int out_size) {
    const int* src_seq = (const int*)d_in[0];
    const int* trg_seq = (const int*)d_in[1];
    const float* src_emb = (const float*)d_in[2];
    const float* trg_emb = (const float*)d_in[3];
    const float* eW0f = (const float*)d_in[4];
    const float* eU0f = (const float*)d_in[5];
    const float* eb0f = (const float*)d_in[6];
    const float* eW0b = (const float*)d_in[7];
    const float* eU0b = (const float*)d_in[8];
    const float* eb0b = (const float*)d_in[9];
    const float* eW1f = (const float*)d_in[10];
    const float* eU1f = (const float*)d_in[11];
    const float* eb1f = (const float*)d_in[12];
    const float* eW1b = (const float*)d_in[13];
    const float* eU1b = (const float*)d_in[14];
    const float* eb1b = (const float*)d_in[15];
    const float* out_W = (const float*)d_in[16];
    const float* out_b = (const float*)d_in[17];
    const float* hpW = (const float*)d_in[18];
    const float* hpb = (const float*)d_in[19];
    const float* cpW = (const float*)d_in[20];
    const float* cpb = (const float*)d_in[21];
    const float* dW0 = (const float*)d_in[22];
    const float* dU0 = (const float*)d_in[23];
    const float* db0 = (const float*)d_in[24];
    const float* dW1 = (const float*)d_in[25];
    const float* dU1 = (const float*)d_in[26];
    const float* db1 = (const float*)d_in[27];
    const float* fcW = (const float*)d_in[28];
    const float* fcb = (const float*)d_in[29];
    float* out = (float*)d_out;

    float* g = nullptr;
    cudaGetSymbolAddress((void**)&g, g_buf);
    unsigned* bar = nullptr;
    cudaGetSymbolAddress((void**)&bar, g_barrier);

    cudaFuncSetAttribute(scan_kernel, cudaFuncAttributeMaxDynamicSharedMemorySize, SMEM_SCAN);
    cudaFuncSetAttribute(attention_kernel, cudaFuncAttributeMaxDynamicSharedMemorySize, SMEM_ATT);
    cudaFuncSetAttribute(gemm_mma_kernel, cudaFuncAttributeMaxDynamicSharedMemorySize, GEMM3_SMEM);
    cudaFuncSetAttribute(gemm_f16_kernel, cudaFuncAttributeMaxDynamicSharedMemorySize, GEMM2_SMEM);

    float* embS = g + OFF_EMBS;
    float* embT = g + OFF_EMBT;
    float* xpA = g + OFF_XPA;
    float* xpB = g + OFF_XPB;
    float* enco = g + OFF_ENCO;
    float* comb = g + OFF_COMB;
    float* hbuf = g + OFF_HBUF;
    float* zero = g + OFF_ZERO;
    float* dscr = g + OFF_DSCR;
    __nv_bfloat16* pool = (__nv_bfloat16*)(g + OFF_POOL);
    __nv_bfloat16* actH = pool + PB_ACTH;
    __nv_bfloat16* actL = pool + PB_ACTL;
    __half* fcWh16 = (__half*)(pool + PB_FCWH);
    __half* fcWl16 = (__half*)(pool + PB_FCWL);
    __half* combA16 = (__half*)(pool + PB_ACTH);

    // Launch order: slots 4 and 6 are gemm_mma (for the ncu -s 5 window).
    embed_kernel<<<NB * NS, 64>>>(src_seq, src_emb, embS);                         // 1
    split_kernel<<<SPG(196608), 256>>>(embS, pool + PB_EMBSH, pool + PB_EMBSL,
                                       196608);                                   // 2
    split_kernel<<<SPG(131072), 256>>>(eW0f, pool + PB_EW0FH, pool + PB_EW0FL,
                                       131072);                                   // 3
    gemm_mma_kernel<<<dim3(24, 16), 256, GEMM3_SMEM>>>(
        pool + PB_EMBSH, pool + PB_EMBSL, pool + PB_EW0FH, pool + PB_EW0FL,
        eb0f, xpA, 3072, 2048, 256);                                              // 4
    split_kernel<<<SPG(131072), 256>>>(eW0b, pool + PB_EW0BH, pool + PB_EW0BL,
                                       131072);                                   // 5
    gemm_mma_kernel<<<dim3(24, 16), 256, GEMM3_SMEM>>>(
        pool + PB_EMBSH, pool + PB_EMBSL, pool + PB_EW0BH, pool + PB_EW0BL,
        eb0b, xpB, 3072, 2048, 256);                                              // 6
    cudaMemsetAsync(bar, 0, 32);
    embed_kernel<<<NB * NS, 64>>>(trg_seq, trg_emb, embT);
    split_kernel<<<SPG(196608), 256>>>(embT, pool + PB_EMBTH, pool + PB_EMBTL, 196608);
    split_kernel<<<SPG(524288), 256>>>(eW1f, pool + PB_EW1FH, pool + PB_EW1FL, 524288);
    split_kernel<<<SPG(524288), 256>>>(eW1b, pool + PB_EW1BH, pool + PB_EW1BL, 524288);
    split_kernel<<<SPG(131072), 256>>>(dW0, pool + PB_DW0H, pool + PB_DW0L, 131072);
    split_kernel<<<SPG(262144), 256>>>(dW1, pool + PB_DW1H, pool + PB_DW1L, 262144);
    split_kernel<<<SPG(131072), 256>>>(out_W, pool + PB_OWH, pool + PB_OWL, 131072);
    split16_pair_kernel<<<SPG(8192000), 256>>>(fcW, fcWh16, fcWl16, 8192000, 512.0f);

    // ---------------- encoder ----------------
    for (int l = 0; l < 2; l++) {
        if (l == 1) {
            // layer-1 x-projections read enc1 bf16 planes written by layer-0 scan
            gemm_mma_kernel<<<dim3(24, 16), 256, GEMM3_SMEM>>>(
                actH, actL, pool + PB_EW1FH, pool + PB_EW1FL, eb1f, xpA, 3072, 2048, 1024);
            gemm_mma_kernel<<<dim3(24, 16), 256, GEMM3_SMEM>>>(
                actH, actL, pool + PB_EW1BH, pool + PB_EW1BL, eb1b, xpB, 3072, 2048, 1024);
        }
        float* hT = g + OFF_HT + (size_t)l * 32768u;
        float* cT = g + OFF_CT + (size_t)l * 32768u;
        ScanArgs f, r;
        f.xp = xpA; f.U = l ? eU1f : eU0f; f.h_init = zero; f.c_init = zero;
        f.hb0 = hbuf; f.hb1 = hbuf + 16384;
        f.hs = nullptr; f.hsH = actH; f.hsL = actL; f.hsF16 = nullptr;
        f.hT = hT; f.cT = cT; f.reverse = 0; f.hsStride = 1024;
        r.xp = xpB; r.U = l ? eU1b : eU0b; r.h_init = zero; r.c_init = zero;
        r.hb0 = hbuf + 32768; r.hb1 = hbuf + 49152;
        r.hs = nullptr; r.hsH = actH + 512; r.hsL = actL + 512; r.hsF16 = nullptr;
        r.hT = hT + 512; r.cT = cT + 512; r.reverse = 1; r.hsStride = 1024;
        scan_kernel<<<256, 256, SMEM_SCAN>>>(f, r, 2, bar + 2 * l);
    }

    // enc_out (N=512, K=1024) reads enc2 bf16 planes from the layer-1 scan
    gemm_mma_kernel<<<dim3(24, 4), 256, GEMM3_SMEM>>>(
        actH, actL, pool + PB_OWH, pool + PB_OWL, out_b, enco, 3072, 512, 1024);

    // bridge (tiny, fp32)
    for (int l = 0; l < 2; l++) {
        sgemm_kernel<<<dim3(4, 1), 256>>>(g + OFF_HT + (size_t)l * 32768u,
                                          hpW + (size_t)l * 524288u, hpb + l * 512,
                                          g + OFF_DH0 + (size_t)l * 16384u, NB, NH, 1024);
        sgemm_kernel<<<dim3(4, 1), 256>>>(g + OFF_CT + (size_t)l * 32768u,
                                          cpW + (size_t)l * 524288u, cpb + l * 512,
                                          g + OFF_DC0 + (size_t)l * 16384u, NB, NH, 1024);
    }

    // ---------------- decoder ----------------
    for (int l = 0; l < 2; l++) {
        const __nv_bfloat16 *xh, *xl;
        int K;
        if (l == 0) { xh = pool + PB_EMBTH; xl = pool + PB_EMBTL; K = 256; }
        else { xh = actH; xl = actL; K = 512; }  // dec0 planes from layer-0 scan
        gemm_mma_kernel<<<dim3(24, 16), 256, GEMM3_SMEM>>>(
            xh, xl, l ? pool + PB_DW1H : pool + PB_DW0H,
            l ? pool + PB_DW1L : pool + PB_DW0L, l ? db1 : db0, xpA, 3072, 2048, K);
        ScanArgs a;
        a.xp = xpA; a.U = l ? dU1 : dU0;
        a.h_init = g + OFF_DH0 + (size_t)l * 16384u;
        a.c_init = g + OFF_DC0 + (size_t)l * 16384u;
        a.hb0 = hbuf; a.hb1 = hbuf + 16384;
        if (l == 0) {
            a.hs = nullptr; a.hsH = actH; a.hsL = actL; a.hsF16 = nullptr;
            a.hsStride = 512;
        } else {
            a.hs = comb; a.hsH = nullptr; a.hsL = nullptr; a.hsF16 = combA16;
            a.hsStride = 1024;
        }
        a.hT = dscr; a.cT = dscr + 32768;
        a.reverse = 0;
        scan_kernel<<<128, 256, SMEM_SCAN>>>(a, a, 1, bar + 4 + l);
    }

    // attention -> comb[:,512:] fp32 + combA16[:,512:] fp16
    attention_kernel<<<dim3(32, 12), 128, SMEM_ATT>>>(enco, src_seq, comb, combA16);

    // logits: fp16 A single-plane, fp16 B hi/lo (B pre-scaled by 512)
    gemm_f16_kernel<<<dim3(24, 250), 256, GEMM2_SMEM>>>(
        combA16, fcWh16, fcWl16, fcb, out, 3072, NV, 1024, 1.0f / 512.0f);
}

// round 9
// speedup vs baseline: 1.6543x; 1.6543x over previous
#include <cuda_runtime.h>
#include <cuda_bf16.h>
#include <cuda_fp16.h>
#include <math.h>
#include <stdint.h>

#define NB 32
#define NS 96
#define NH 512
#define G4H 2048
#define NV 32000

// ---------------- float scratch offsets ----------------
#define OFF_EMBS 0u
#define OFF_EMBT (OFF_EMBS + 786432u)
#define OFF_XPA  (OFF_EMBT + 786432u)
#define OFF_XPB  (OFF_XPA + 6291456u)
#define OFF_ENC1 (OFF_XPB + 6291456u)
#define OFF_ENC2 (OFF_ENC1 + 3145728u)
#define OFF_ENCO (OFF_ENC2 + 3145728u)
#define OFF_DEC0 (OFF_ENCO + 1572864u)
#define OFF_COMB (OFF_DEC0 + 1572864u)
#define OFF_HT   (OFF_COMB + 3145728u)
#define OFF_CT   (OFF_HT + 65536u)
#define OFF_DH0  (OFF_CT + 65536u)
#define OFF_DC0  (OFF_DH0 + 32768u)
#define OFF_HBUF (OFF_DC0 + 32768u)
#define OFF_ZERO (OFF_HBUF + 65536u)
#define OFF_DSCR (OFF_ZERO + 16384u)
#define OFF_POOL (OFF_DSCR + 65536u)
// ---------------- 16-bit pool offsets (elements) ----------------
#define PB_FCWH 0u
#define PB_FCWL 32768000u
#define PB_W    65536000u
#define PB_EW0FH (PB_W + 0u)
#define PB_EW0FL (PB_W + 524288u)
#define PB_EW0BH (PB_W + 1048576u)
#define PB_EW0BL (PB_W + 1572864u)
#define PB_EW1FH (PB_W + 2097152u)
#define PB_EW1FL (PB_W + 4194304u)
#define PB_EW1BH (PB_W + 6291456u)
#define PB_EW1BL (PB_W + 8388608u)
#define PB_DW0H  (PB_W + 10485760u)
#define PB_DW0L  (PB_W + 11010048u)
#define PB_DW1H  (PB_W + 11534336u)
#define PB_DW1L  (PB_W + 12582912u)
#define PB_OWH   (PB_W + 13631488u)
#define PB_OWL   (PB_W + 14155776u)
#define PB_ACTH  80216064u
#define PB_ACTL  83361792u
#define PB_EMBSH 86507520u
#define PB_EMBSL 87293952u
#define PB_EMBTH 88080384u
#define PB_EMBTL 88866816u
#define POOL_BF16 89653248u

#define TOTALF (OFF_POOL + (POOL_BF16 + 1u) / 2u + 64u)

__device__ __align__(128) float g_buf[TOTALF];
__device__ unsigned g_barrier[4];

// =================== helpers ===================
__device__ __forceinline__ uint32_t smem_to_u32(const void* p) {
    uint32_t a;
    asm("{ .reg .u64 t; cvta.to.shared.u64 t, %1; cvt.u32.u64 %0, t; }" : "=r"(a) : "l"(p));
    return a;
}
#define CP16(dst, src) asm volatile( \
    "cp.async.cg.shared.global [%0], [%1], 16;" :: "r"(dst), "l"(src))
#define CP_COMMIT() asm volatile("cp.async.commit_group;")
#define CP_WAIT1() asm volatile("cp.async.wait_group 1;")

__device__ __forceinline__ void mma_bf16(float* c, const uint32_t* a, const uint32_t* b) {
    asm volatile(
        "mma.sync.aligned.m16n8k16.row.col.f32.bf16.bf16.f32 "
        "{%0,%1,%2,%3}, {%4,%5,%6,%7}, {%8,%9}, {%0,%1,%2,%3};"
        : "+f"(c[0]), "+f"(c[1]), "+f"(c[2]), "+f"(c[3])
        : "r"(a[0]), "r"(a[1]), "r"(a[2]), "r"(a[3]), "r"(b[0]), "r"(b[1]));
}
__device__ __forceinline__ void mma_f16(float* c, const uint32_t* a, const uint32_t* b) {
    asm volatile(
        "mma.sync.aligned.m16n8k16.row.col.f32.f16.f16.f32 "
        "{%0,%1,%2,%3}, {%4,%5,%6,%7}, {%8,%9}, {%0,%1,%2,%3};"
        : "+f"(c[0]), "+f"(c[1]), "+f"(c[2]), "+f"(c[3])
        : "r"(a[0]), "r"(a[1]), "r"(a[2]), "r"(a[3]), "r"(b[0]), "r"(b[1]));
}

// ---------------- embedding gather ----------------
__global__ void embed_kernel(const int* __restrict__ seq, const float* __restrict__ emb,
                             float* __restrict__ out) {
    int tok = blockIdx.x;
    int id = seq[tok];
    const float4* s = (const float4*)(emb + (size_t)id * 256);
    float4* d = (float4*)(out + (size_t)tok * 256);
    d[threadIdx.x] = s[threadIdx.x];
}

// ---------------- fp32 -> bf16 hi/lo (4-way ILP) ----------------
__device__ __forceinline__ void bf_split1(float4 v, __nv_bfloat162* H, __nv_bfloat162* L,
                                          int i) {
    __nv_bfloat16 h0 = __float2bfloat16(v.x), h1 = __float2bfloat16(v.y);
    __nv_bfloat16 h2 = __float2bfloat16(v.z), h3 = __float2bfloat16(v.w);
    H[i * 2] = __nv_bfloat162(h0, h1);
    H[i * 2 + 1] = __nv_bfloat162(h2, h3);
    L[i * 2] = __nv_bfloat162(__float2bfloat16(v.x - __bfloat162float(h0)),
                              __float2bfloat16(v.y - __bfloat162float(h1)));
    L[i * 2 + 1] = __nv_bfloat162(__float2bfloat16(v.z - __bfloat162float(h2)),
                                  __float2bfloat16(v.w - __bfloat162float(h3)));
}

__global__ void split_kernel(const float* __restrict__ in, __nv_bfloat16* __restrict__ hi,
                             __nv_bfloat16* __restrict__ lo, int n4) {
    int tot = gridDim.x * 256;
    __nv_bfloat162* H = (__nv_bfloat162*)hi;
    __nv_bfloat162* L = (__nv_bfloat162*)lo;
    for (int t = blockIdx.x * 256 + threadIdx.x; t < n4; t += 4 * tot) {
        int i1 = t + tot, i2 = t + 2 * tot, i3 = t + 3 * tot;
        float4 v0 = ((const float4*)in)[t];
        float4 v1, v2, v3;
        if (i1 < n4) v1 = ((const float4*)in)[i1];
        if (i2 < n4) v2 = ((const float4*)in)[i2];
        if (i3 < n4) v3 = ((const float4*)in)[i3];
        bf_split1(v0, H, L, t);
        if (i1 < n4) bf_split1(v1, H, L, i1);
        if (i2 < n4) bf_split1(v2, H, L, i2);
        if (i3 < n4) bf_split1(v3, H, L, i3);
    }
}

// ---------------- fp32 -> fp16 hi/lo with pre-scale ----------------
__device__ __forceinline__ void f16_split1(float4 v, __half2* H, __half2* L, int i,
                                           float scale) {
    float x0 = v.x * scale, x1 = v.y * scale, x2 = v.z * scale, x3 = v.w * scale;
    __half h0 = __float2half_rn(x0), h1 = __float2half_rn(x1);
    __half h2 = __float2half_rn(x2), h3 = __float2half_rn(x3);
    H[i * 2] = __half2(h0, h1);
    H[i * 2 + 1] = __half2(h2, h3);
    L[i * 2] = __half2(__float2half_rn(x0 - __half2float(h0)),
                       __float2half_rn(x1 - __half2float(h1)));
    L[i * 2 + 1] = __half2(__float2half_rn(x2 - __half2float(h2)),
                           __float2half_rn(x3 - __half2float(h3)));
}

__global__ void split16_pair_kernel(const float* __restrict__ in, __half* __restrict__ hi,
                                    __half* __restrict__ lo, int n4, float scale) {
    int tot = gridDim.x * 256;
    __half2* H = (__half2*)hi;
    __half2* L = (__half2*)lo;
    for (int t = blockIdx.x * 256 + threadIdx.x; t < n4; t += 4 * tot) {
        int i1 = t + tot, i2 = t + 2 * tot, i3 = t + 3 * tot;
        float4 v0 = ((const float4*)in)[t];
        float4 v1, v2, v3;
        if (i1 < n4) v1 = ((const float4*)in)[i1];
        if (i2 < n4) v2 = ((const float4*)in)[i2];
        if (i3 < n4) v3 = ((const float4*)in)[i3];
        f16_split1(v0, H, L, t, scale);
        if (i1 < n4) f16_split1(v1, H, L, i1, scale);
        if (i2 < n4) f16_split1(v2, H, L, i2, scale);
        if (i3 < n4) f16_split1(v3, H, L, i3, scale);
    }
}

// ---------------- fp32 -> fp16 single ----------------
__global__ void split16_one_kernel(const float* __restrict__ in, __half* __restrict__ hi,
                                   int n4) {
    int tot = gridDim.x * 256;
    __half2* H = (__half2*)hi;
    for (int t = blockIdx.x * 256 + threadIdx.x; t < n4; t += 4 * tot) {
#pragma unroll
        for (int u = 0; u < 4; u++) {
            int i = t + u * tot;
            if (i < n4) {
                float4 v = ((const float4*)in)[i];
                H[i * 2] = __half2(__float2half_rn(v.x), __float2half_rn(v.y));
                H[i * 2 + 1] = __half2(__float2half_rn(v.z), __float2half_rn(v.w));
            }
        }
    }
}

// ---------------- merged bridge GEMM: 4 jobs of C[32,512]=A[32,1024]@W^T+b ----------------
struct B4 { const float *A, *W, *bi; float* C; };

__global__ void __launch_bounds__(256) bridge_kernel(B4 j0, B4 j1, B4 j2, B4 j3) {
    B4 j = (blockIdx.y == 0) ? j0 : (blockIdx.y == 1) ? j1 : (blockIdx.y == 2) ? j2 : j3;
    __shared__ __align__(16) float As[8][128];
    __shared__ __align__(16) float Bs[8][128];
    const int M = 32, N = 512, K = 1024;
    int tid = threadIdx.x;
    int bn = blockIdx.x;
    int row = tid >> 1, kq = (tid & 1) * 4;
    int gn = bn * 128 + row;
    int tx = tid & 15, ty = tid >> 4;
    bool am = row < M;
    const float* Ap = j.A + (size_t)row * K + kq;
    const float* Bp = j.W + (size_t)gn * K + kq;
    float acc[8][8];
#pragma unroll
    for (int i = 0; i < 8; i++)
#pragma unroll
        for (int jj = 0; jj < 8; jj++) acc[i][jj] = 0.f;
    for (int k0 = 0; k0 < K; k0 += 8) {
        float4 av = am ? *(const float4*)(Ap + k0) : make_float4(0, 0, 0, 0);
        float4 bv = *(const float4*)(Bp + k0);
        __syncthreads();
        As[kq + 0][row] = av.x; As[kq + 1][row] = av.y;
        As[kq + 2][row] = av.z; As[kq + 3][row] = av.w;
        Bs[kq + 0][row] = bv.x; Bs[kq + 1][row] = bv.y;
        Bs[kq + 2][row] = bv.z; Bs[kq + 3][row] = bv.w;
        __syncthreads();
#pragma unroll
        for (int kk = 0; kk < 8; kk++) {
            float4 a0 = *(const float4*)&As[kk][ty * 8];
            float4 a1 = *(const float4*)&As[kk][ty * 8 + 4];
            float4 b0 = *(const float4*)&Bs[kk][tx * 8];
            float4 b1 = *(const float4*)&Bs[kk][tx * 8 + 4];
            float a[8] = {a0.x, a0.y, a0.z, a0.w, a1.x, a1.y, a1.z, a1.w};
            float b[8] = {b0.x, b0.y, b0.z, b0.w, b1.x, b1.y, b1.z, b1.w};
#pragma unroll
            for (int i = 0; i < 8; i++)
#pragma unroll
                for (int jj = 0; jj < 8; jj++) acc[i][jj] = fmaf(a[i], b[jj], acc[i][jj]);
        }
    }
#pragma unroll
    for (int i = 0; i < 8; i++) {
        int m = ty * 8 + i;
        if (m >= M) continue;
#pragma unroll
        for (int jj = 0; jj < 8; jj++) {
            int n = bn * 128 + tx * 8 + jj;
            j.C[(size_t)m * N + n] = acc[i][jj] + j.bi[n];
        }
    }
}

// ---------------- bf16 3-product GEMM (A hi/lo, B hi/lo) ----------------
#define PLB 10240
#define STB (4 * PLB)
#define GEMM3_SMEM (2 * STB)

__device__ __forceinline__ void issue_stage4(
    uint32_t d, const __nv_bfloat16* a0, const __nv_bfloat16* a1,
    const __nv_bfloat16* b0, const __nv_bfloat16* b1) {
    CP16(d, a0);                 CP16(d + 16, a0 + 8);
    CP16(d + PLB, a1);           CP16(d + PLB + 16, a1 + 8);
    CP16(d + 2 * PLB, b0);       CP16(d + 2 * PLB + 16, b0 + 8);
    CP16(d + 3 * PLB, b1);       CP16(d + 3 * PLB + 16, b1 + 8);
}

__global__ void __launch_bounds__(256, 2) gemm_mma_kernel(
    const __nv_bfloat16* __restrict__ Ah, const __nv_bfloat16* __restrict__ Al,
    const __nv_bfloat16* __restrict__ Bh, const __nv_bfloat16* __restrict__ Bl,
    const float* __restrict__ bias, float* __restrict__ C, int M, int N, int K) {
    extern __shared__ __align__(16) char smraw[];
    uint32_t sb = smem_to_u32(smraw);
    const uint32_t* sw = (const uint32_t*)smraw;
    int tid = threadIdx.x;
    int wid = tid >> 5, lane = tid & 31;
    int m0 = blockIdx.x * 128, n0 = blockIdx.y * 128;
    int wm = (wid >> 2) * 64, wn = (wid & 3) * 32;
    int tp = lane >> 2, tq = lane & 3;

    int row = tid >> 1;
    int cpair = (tid & 1) * 2;
    const __nv_bfloat16* gA0 = Ah + (size_t)(m0 + row) * K + cpair * 8;
    const __nv_bfloat16* gA1 = Al + (size_t)(m0 + row) * K + cpair * 8;
    const __nv_bfloat16* gB0 = Bh + (size_t)(n0 + row) * K + cpair * 8;
    const __nv_bfloat16* gB1 = Bl + (size_t)(n0 + row) * K + cpair * 8;
    uint32_t dthr = sb + row * 80 + cpair * 16;

    float acc[4][4][4];
#pragma unroll
    for (int mt = 0; mt < 4; mt++)
#pragma unroll
        for (int nt = 0; nt < 4; nt++)
#pragma unroll
            for (int q = 0; q < 4; q++) acc[mt][nt][q] = 0.f;

    int nst = K / 32;
    issue_stage4(dthr, gA0, gA1, gB0, gB1);
    CP_COMMIT();
    for (int s = 0; s < nst; s++) {
        if (s + 1 < nst) {
            int k0 = (s + 1) * 32;
            issue_stage4(dthr + ((s + 1) & 1) * STB, gA0 + k0, gA1 + k0, gB0 + k0, gB1 + k0);
        }
        CP_COMMIT();
        CP_WAIT1();
        __syncthreads();
        int base = ((s & 1) * STB) >> 2;
#pragma unroll
        for (int kk = 0; kk < 2; kk++) {
            uint32_t bfr[2][4][2];
#pragma unroll
            for (int p = 0; p < 2; p++)
#pragma unroll
                for (int nt = 0; nt < 4; nt++) {
                    int r = wn + nt * 8 + tp;
                    int w0 = base + 5120 + p * 2560 + r * 20 + kk * 8 + tq;
                    bfr[p][nt][0] = sw[w0];
                    bfr[p][nt][1] = sw[w0 + 4];
                }
            uint32_t af[4][4];
#pragma unroll
            for (int mt = 0; mt < 4; mt++) {
                int r = wm + mt * 16 + tp;
                int w0 = base + r * 20 + kk * 8 + tq;
                af[mt][0] = sw[w0]; af[mt][1] = sw[w0 + 160];
                af[mt][2] = sw[w0 + 4]; af[mt][3] = sw[w0 + 164];
            }
#pragma unroll
            for (int mt = 0; mt < 4; mt++)
#pragma unroll
                for (int nt = 0; nt < 4; nt++) {
                    mma_bf16(acc[mt][nt], af[mt], bfr[0][nt]);
                    mma_bf16(acc[mt][nt], af[mt], bfr[1][nt]);
                }
#pragma unroll
            for (int mt = 0; mt < 4; mt++) {
                int r = wm + mt * 16 + tp;
                int w0 = base + 2560 + r * 20 + kk * 8 + tq;
                af[mt][0] = sw[w0]; af[mt][1] = sw[w0 + 160];
                af[mt][2] = sw[w0 + 4]; af[mt][3] = sw[w0 + 164];
            }
#pragma unroll
            for (int mt = 0; mt < 4; mt++)
#pragma unroll
                for (int nt = 0; nt < 4; nt++)
                    mma_bf16(acc[mt][nt], af[mt], bfr[0][nt]);
        }
        __syncthreads();
    }
#pragma unroll
    for (int mt = 0; mt < 4; mt++) {
        int r = m0 + wm + mt * 16 + tp;
#pragma unroll
        for (int nt = 0; nt < 4; nt++) {
            int c = n0 + wn + nt * 8 + tq * 2;
            float b0v = bias[c], b1v = bias[c + 1];
            *(float2*)&C[(size_t)r * N + c] =
                make_float2(acc[mt][nt][0] + b0v, acc[mt][nt][1] + b1v);
            *(float2*)&C[(size_t)(r + 8) * N + c] =
                make_float2(acc[mt][nt][2] + b0v, acc[mt][nt][3] + b1v);
        }
    }
}

// ---------------- fp16 2-product GEMM (A single, B hi/lo, C scaled) ----------------
#define PLB2 10240
#define STB2 (3 * PLB2)
#define GEMM2_SMEM (2 * STB2)

__global__ void __launch_bounds__(256, 2) gemm_f16_kernel(
    const __half* __restrict__ Aa, const __half* __restrict__ Bh,
    const __half* __restrict__ Bl, const float* __restrict__ bias,
    float* __restrict__ C, int M, int N, int K, float outScale) {
    extern __shared__ __align__(16) char smraw[];
    uint32_t sb = smem_to_u32(smraw);
    const uint32_t* sw = (const uint32_t*)smraw;
    int tid = threadIdx.x;
    int wid = tid >> 5, lane = tid & 31;
    int m0 = blockIdx.x * 128, n0 = blockIdx.y * 128;
    int wm = (wid >> 2) * 64, wn = (wid & 3) * 32;
    int tp = lane >> 2, tq = lane & 3;

    int row = tid >> 1;
    int cpair = (tid & 1) * 2;
    const __half* gA = Aa + (size_t)(m0 + row) * K + cpair * 8;
    const __half* gB0 = Bh + (size_t)(n0 + row) * K + cpair * 8;
    const __half* gB1 = Bl + (size_t)(n0 + row) * K + cpair * 8;
    uint32_t dthr = sb + row * 80 + cpair * 16;

    float acc[4][4][4];
#pragma unroll
    for (int mt = 0; mt < 4; mt++)
#pragma unroll
        for (int nt = 0; nt < 4; nt++)
#pragma unroll
            for (int q = 0; q < 4; q++) acc[mt][nt][q] = 0.f;

    int nst = K / 32;
    {
        CP16(dthr, gA); CP16(dthr + 16, gA + 8);
        CP16(dthr + PLB2, gB0); CP16(dthr + PLB2 + 16, gB0 + 8);
        CP16(dthr + 2 * PLB2, gB1); CP16(dthr + 2 * PLB2 + 16, gB1 + 8);
    }
    CP_COMMIT();
    for (int s = 0; s < nst; s++) {
        if (s + 1 < nst) {
            int k0 = (s + 1) * 32;
            uint32_t d = dthr + ((s + 1) & 1) * STB2;
            CP16(d, gA + k0); CP16(d + 16, gA + k0 + 8);
            CP16(d + PLB2, gB0 + k0); CP16(d + PLB2 + 16, gB0 + k0 + 8);
            CP16(d + 2 * PLB2, gB1 + k0); CP16(d + 2 * PLB2 + 16, gB1 + k0 + 8);
        }
        CP_COMMIT();
        CP_WAIT1();
        __syncthreads();
        int base = ((s & 1) * STB2) >> 2;
#pragma unroll
        for (int kk = 0; kk < 2; kk++) {
            uint32_t bfr[2][4][2];
#pragma unroll
            for (int p = 0; p < 2; p++)
#pragma unroll
                for (int nt = 0; nt < 4; nt++) {
                    int r = wn + nt * 8 + tp;
                    int w0 = base + 2560 + p * 2560 + r * 20 + kk * 8 + tq;
                    bfr[p][nt][0] = sw[w0];
                    bfr[p][nt][1] = sw[w0 + 4];
                }
            uint32_t af[4][4];
#pragma unroll
            for (int mt = 0; mt < 4; mt++) {
                int r = wm + mt * 16 + tp;
                int w0 = base + r * 20 + kk * 8 + tq;
                af[mt][0] = sw[w0]; af[mt][1] = sw[w0 + 160];
                af[mt][2] = sw[w0 + 4]; af[mt][3] = sw[w0 + 164];
            }
#pragma unroll
            for (int mt = 0; mt < 4; mt++)
#pragma unroll
                for (int nt = 0; nt < 4; nt++) {
                    mma_f16(acc[mt][nt], af[mt], bfr[0][nt]);
                    mma_f16(acc[mt][nt], af[mt], bfr[1][nt]);
                }
        }
        __syncthreads();
    }
#pragma unroll
    for (int mt = 0; mt < 4; mt++) {
        int r = m0 + wm + mt * 16 + tp;
#pragma unroll
        for (int nt = 0; nt < 4; nt++) {
            int c = n0 + wn + nt * 8 + tq * 2;
            float b0v = bias[c], b1v = bias[c + 1];
            *(float2*)&C[(size_t)r * N + c] =
                make_float2(acc[mt][nt][0] * outScale + b0v, acc[mt][nt][1] * outScale + b1v);
            *(float2*)&C[(size_t)(r + 8) * N + c] =
                make_float2(acc[mt][nt][2] * outScale + b0v, acc[mt][nt][3] * outScale + b1v);
        }
    }
}

// ---------------- persistent LSTM scan (round-6 proven form) ----------------
struct ScanArgs {
    const float* xp;
    const float* U;
    const float* h_init;
    const float* c_init;
    float* hb0; float* hb1;
    float* hs;
    float* hT; float* cT;
    int reverse; int hsStride;
};

__device__ __forceinline__ float sigm(float x) { return 1.f / (1.f + expf(-x)); }

#define HCB 4
#define SPITCH 532
#define KHALF 272
#define SMEM_SCAN ((16 + 32) * SPITCH * 4)

__global__ void __launch_bounds__(256) scan_kernel(ScanArgs A0, ScanArgs A1, int nDir,
                                                   unsigned* bar) {
    extern __shared__ float sm[];
    int bpd = gridDim.x / nDir;
    ScanArgs a = (blockIdx.x / bpd) ? A1 : A0;
    int hc0 = (blockIdx.x % bpd) * HCB;
    int tid = threadIdx.x;
    float* sW = sm;                    // [16][SPITCH]
    float* sh = sm + 16 * SPITCH;      // [32][SPITCH]
    for (int i = tid; i < 16 * 128; i += 256) {
        int r = i >> 7, k4 = (i & 127) * 4;
        int kst = k4 + (k4 >= 256 ? (KHALF - 256) : 0);
        int gg = r >> 2, hc = r & 3;
        *(float4*)&sW[r * SPITCH + kst] =
            *(const float4*)(a.U + ((size_t)(gg * 512 + hc0 + hc)) * 512 + k4);
    }
    int b = tid >> 3;
    int sub = (tid >> 2) & 1;
    int hc = tid & 3;
    int kbo = sub * KHALF;
    float creg = a.c_init[b * 512 + hc0 + hc];
    const float* w_i = &sW[(0 * HCB + hc) * SPITCH + kbo];
    const float* w_f = &sW[(1 * HCB + hc) * SPITCH + kbo];
    const float* w_g = &sW[(2 * HCB + hc) * SPITCH + kbo];
    const float* w_o = &sW[(3 * HCB + hc) * SPITCH + kbo];

    for (int t = 0; t < 96; t++) {
        const float* hsrc = (t == 0) ? a.h_init : ((t & 1) ? a.hb1 : a.hb0);
        __syncthreads();
        for (int i = tid; i < 32 * 128; i += 256) {
            int bb = i >> 7, k4 = (i & 127) * 4;
            int kst = k4 + (k4 >= 256 ? (KHALF - 256) : 0);
            float4 v = __ldcv((const float4*)(hsrc + bb * 512 + k4));
            *(float4*)&sh[bb * SPITCH + kst] = v;
        }
        __syncthreads();
        float ai = 0, af = 0, ag = 0, ao = 0;
        const float* hrow = &sh[b * SPITCH + kbo];
#pragma unroll 4
        for (int k = 0; k < 256; k += 4) {
            float4 hv = *(const float4*)&hrow[k];
            float4 wi = *(const float4*)&w_i[k];
            float4 wf = *(const float4*)&w_f[k];
            float4 wg = *(const float4*)&w_g[k];
            float4 wo = *(const float4*)&w_o[k];
            ai = fmaf(hv.x, wi.x, ai); ai = fmaf(hv.y, wi.y, ai);
            ai = fmaf(hv.z, wi.z, ai); ai = fmaf(hv.w, wi.w, ai);
            af = fmaf(hv.x, wf.x, af); af = fmaf(hv.y, wf.y, af);
            af = fmaf(hv.z, wf.z, af); af = fmaf(hv.w, wf.w, af);
            ag = fmaf(hv.x, wg.x, ag); ag = fmaf(hv.y, wg.y, ag);
            ag = fmaf(hv.z, wg.z, ag); ag = fmaf(hv.w, wg.w, ag);
            ao = fmaf(hv.x, wo.x, ao); ao = fmaf(hv.y, wo.y, ao);
            ao = fmaf(hv.z, wo.z, ao); ao = fmaf(hv.w, wo.w, ao);
        }
        ai += __shfl_xor_sync(~0u, ai, 4);
        af += __shfl_xor_sync(~0u, af, 4);
        ag += __shfl_xor_sync(~0u, ag, 4);
        ao += __shfl_xor_sync(~0u, ao, 4);
        if (sub == 0) {
            int tsrc = a.reverse ? 95 - t : t;
            const float* xr = a.xp + ((size_t)(b * 96 + tsrc)) * 2048 + hc0 + hc;
            float gi = ai + xr[0], gf = af + xr[512];
            float gg2 = ag + xr[1024], go = ao + xr[1536];
            creg = sigm(gf) * creg + sigm(gi) * tanhf(gg2);
            float hn = sigm(go) * tanhf(creg);
            float* hdst = (t & 1) ? a.hb0 : a.hb1;
            hdst[b * 512 + hc0 + hc] = hn;
            a.hs[((size_t)(b * 96 + tsrc)) * a.hsStride + hc0 + hc] = hn;
            if (t == 95) {
                a.hT[b * 1024 + hc0 + hc] = hn;
                a.cT[b * 1024 + hc0 + hc] = creg;
            }
        }
        if (t < 95) {
            __threadfence();
            __syncthreads();
            if (tid == 0) {
                atomicAdd(bar, 1u);
                unsigned target = gridDim.x * (unsigned)(t + 1);
                while (*((volatile unsigned*)bar) < target) { }
                __threadfence();
            }
            __syncthreads();
        }
    }
}

// ---------------- fused attention ----------------
#define ATT_SE 0
#define ATT_SY (96 * 513)
#define ATT_AT (ATT_SY + 512)
#define ATT_MK (ATT_AT + 96)
#define ATT_RD (ATT_MK + 96)
#define SMEM_ATT ((ATT_RD + 2) * 4)

__global__ void __launch_bounds__(128) attention_kernel(
    const float* __restrict__ encout, const int* __restrict__ src, float* __restrict__ comb) {
    extern __shared__ float sh[];
    float* se = sh + ATT_SE;
    float* sy = sh + ATT_SY;
    float* sAttn = sh + ATT_AT;
    float* sMask = sh + ATT_MK;
    float* sRed = sh + ATT_RD;
    int b = blockIdx.x, tchunk = blockIdx.y, tid = threadIdx.x;
    for (int i = tid; i < 96 * 128; i += 128) {
        int r = i >> 7, c4 = (i & 127) << 2;
        float4 v = *(const float4*)(encout + ((size_t)(b * NS + r)) * NH + c4);
        float* d = se + r * 513 + c4;
        d[0] = v.x; d[1] = v.y; d[2] = v.z; d[3] = v.w;
    }
    if (tid < 96) sMask[tid] = (src[b * NS + tid] != 0) ? 1.f : 0.f;
    __syncthreads();
    for (int tt = 0; tt < 8; tt++) {
        int t = tchunk * 8 + tt;
        ((float4*)sy)[tid] = *(const float4*)(comb + ((size_t)(b * NS + t)) * 1024 + tid * 4);
        __syncthreads();
        if (tid < 96) {
            float e = 0.f;
            const float* r = se + tid * 513;
#pragma unroll 8
            for (int k = 0; k < NH; k++) e = fmaf(sy[k], r[k], e);
            sAttn[tid] = (sMask[tid] != 0.f) ? e : -1e10f;
        }
        __syncthreads();
        if (tid < 32) {
            float m = fmaxf(sAttn[tid], fmaxf(sAttn[tid + 32], sAttn[tid + 64]));
            for (int o = 16; o > 0; o >>= 1) m = fmaxf(m, __shfl_xor_sync(~0u, m, o));
            if (tid == 0) sRed[0] = m;
        }
        __syncthreads();
        if (tid < 96) sAttn[tid] = expf(sAttn[tid] - sRed[0]);
        __syncthreads();
        if (tid < 32) {
            float sv = sAttn[tid] + sAttn[tid + 32] + sAttn[tid + 64];
            for (int o = 16; o > 0; o >>= 1) sv += __shfl_xor_sync(~0u, sv, o);
            if (tid == 0) sRed[1] = sv;
        }
        __syncthreads();
        float inv = 1.f / sRed[1];
        float a0 = 0, a1 = 0, a2 = 0, a3 = 0;
        for (int s = 0; s < 96; s++) {
            float w = sAttn[s];
            const float* r = se + s * 513;
            a0 = fmaf(w, r[tid], a0);
            a1 = fmaf(w, r[tid + 128], a1);
            a2 = fmaf(w, r[tid + 256], a2);
            a3 = fmaf(w, r[tid + 384], a3);
        }
        float* o = comb + ((size_t)(b * NS + t)) * 1024 + 512;
        o[tid] = a0 * inv; o[tid + 128] = a1 * inv;
        o[tid + 256] = a2 * inv; o[tid + 384] = a3 * inv;
        __syncthreads();
    }
}

// ---------------- host ----------------
#define SPG(n4) (((n4) + 1023) / 1024)

extern "C" void kernel_launch(void* const* d_in, const int* in_sizes, int n_in,
                              void* d_out, int out_size) {
    const int* src_seq = (const int*)d_in[0];
    const int* trg_seq = (const int*)d_in[1];
    const float* src_emb = (const float*)d_in[2];
    const float* trg_emb = (const float*)d_in[3];
    const float* eW0f = (const float*)d_in[4];
    const float* eU0f = (const float*)d_in[5];
    const float* eb0f = (const float*)d_in[6];
    const float* eW0b = (const float*)d_in[7];
    const float* eU0b = (const float*)d_in[8];
    const float* eb0b = (const float*)d_in[9];
    const float* eW1f = (const float*)d_in[10];
    const float* eU1f = (const float*)d_in[11];
    const float* eb1f = (const float*)d_in[12];
    const float* eW1b = (const float*)d_in[13];
    const float* eU1b = (const float*)d_in[14];
    const float* eb1b = (const float*)d_in[15];
    const float* out_W = (const float*)d_in[16];
    const float* out_b = (const float*)d_in[17];
    const float* hpW = (const float*)d_in[18];
    const float* hpb = (const float*)d_in[19];
    const float* cpW = (const float*)d_in[20];
    const float* cpb = (const float*)d_in[21];
    const float* dW0 = (const float*)d_in[22];
    const float* dU0 = (const float*)d_in[23];
    const float* db0 = (const float*)d_in[24];
    const float* dW1 = (const float*)d_in[25];
    const float* dU1 = (const float*)d_in[26];
    const float* db1 = (const float*)d_in[27];
    const float* fcW = (const float*)d_in[28];
    const float* fcb = (const float*)d_in[29];
    float* out = (float*)d_out;

    float* g = nullptr;
    cudaGetSymbolAddress((void**)&g, g_buf);
    unsigned* bar = nullptr;
    cudaGetSymbolAddress((void**)&bar, g_barrier);

    cudaFuncSetAttribute(scan_kernel, cudaFuncAttributeMaxDynamicSharedMemorySize, SMEM_SCAN);
    cudaFuncSetAttribute(attention_kernel, cudaFuncAttributeMaxDynamicSharedMemorySize, SMEM_ATT);
    cudaFuncSetAttribute(gemm_mma_kernel, cudaFuncAttributeMaxDynamicSharedMemorySize, GEMM3_SMEM);
    cudaFuncSetAttribute(gemm_f16_kernel, cudaFuncAttributeMaxDynamicSharedMemorySize, GEMM2_SMEM);

    float* embS = g + OFF_EMBS;
    float* embT = g + OFF_EMBT;
    float* xpA = g + OFF_XPA;
    float* xpB = g + OFF_XPB;
    float* enc1 = g + OFF_ENC1;
    float* enc2 = g + OFF_ENC2;
    float* enco = g + OFF_ENCO;
    float* dec0 = g + OFF_DEC0;
    float* comb = g + OFF_COMB;
    float* hbuf = g + OFF_HBUF;
    float* zero = g + OFF_ZERO;
    float* dscr = g + OFF_DSCR;
    __nv_bfloat16* pool = (__nv_bfloat16*)(g + OFF_POOL);
    __half* fcWh16 = (__half*)(pool + PB_FCWH);
    __half* fcWl16 = (__half*)(pool + PB_FCWL);
    __half* combA16 = (__half*)(pool + PB_ACTH);

    // Launch order: slots 4 and 6 are gemm_mma (ncu -s 5 -c 1 profiles #6).
    embed_kernel<<<NB * NS, 64>>>(src_seq, src_emb, embS);                         // 1
    split_kernel<<<SPG(196608), 256>>>(embS, pool + PB_EMBSH, pool + PB_EMBSL,
                                       196608);                                   // 2
    split_kernel<<<SPG(131072), 256>>>(eW0f, pool + PB_EW0FH, pool + PB_EW0FL,
                                       131072);                                   // 3
    gemm_mma_kernel<<<dim3(24, 16), 256, GEMM3_SMEM>>>(
        pool + PB_EMBSH, pool + PB_EMBSL, pool + PB_EW0FH, pool + PB_EW0FL,
        eb0f, xpA, 3072, 2048, 256);                                              // 4
    split_kernel<<<SPG(131072), 256>>>(eW0b, pool + PB_EW0BH, pool + PB_EW0BL,
                                       131072);                                   // 5
    gemm_mma_kernel<<<dim3(24, 16), 256, GEMM3_SMEM>>>(
        pool + PB_EMBSH, pool + PB_EMBSL, pool + PB_EW0BH, pool + PB_EW0BL,
        eb0b, xpB, 3072, 2048, 256);                                              // 6
    cudaMemsetAsync(bar, 0, 16);
    embed_kernel<<<NB * NS, 64>>>(trg_seq, trg_emb, embT);
    split_kernel<<<SPG(196608), 256>>>(embT, pool + PB_EMBTH, pool + PB_EMBTL, 196608);
    split_kernel<<<SPG(524288), 256>>>(eW1f, pool + PB_EW1FH, pool + PB_EW1FL, 524288);
    split_kernel<<<SPG(524288), 256>>>(eW1b, pool + PB_EW1BH, pool + PB_EW1BL, 524288);
    split_kernel<<<SPG(131072), 256>>>(dW0, pool + PB_DW0H, pool + PB_DW0L, 131072);
    split_kernel<<<SPG(262144), 256>>>(dW1, pool + PB_DW1H, pool + PB_DW1L, 262144);
    split_kernel<<<SPG(131072), 256>>>(out_W, pool + PB_OWH, pool + PB_OWL, 131072);
    split16_pair_kernel<<<SPG(8192000), 256>>>(fcW, fcWh16, fcWl16, 8192000, 512.0f);

    // ---------------- encoder ----------------
    for (int l = 0; l < 2; l++) {
        if (l == 1) {
            split_kernel<<<SPG(786432), 256>>>(enc1, pool + PB_ACTH, pool + PB_ACTL, 786432);
            gemm_mma_kernel<<<dim3(24, 16), 256, GEMM3_SMEM>>>(
                pool + PB_ACTH, pool + PB_ACTL, pool + PB_EW1FH, pool + PB_EW1FL,
                eb1f, xpA, 3072, 2048, 1024);
            gemm_mma_kernel<<<dim3(24, 16), 256, GEMM3_SMEM>>>(
                pool + PB_ACTH, pool + PB_ACTL, pool + PB_EW1BH, pool + PB_EW1BL,
                eb1b, xpB, 3072, 2048, 1024);
        }
        float* hs = l ? enc2 : enc1;
        float* hT = g + OFF_HT + (size_t)l * 32768u;
        float* cT = g + OFF_CT + (size_t)l * 32768u;
        ScanArgs f, r;
        f.xp = xpA; f.U = l ? eU1f : eU0f; f.h_init = zero; f.c_init = zero;
        f.hb0 = hbuf; f.hb1 = hbuf + 16384;
        f.hs = hs; f.hT = hT; f.cT = cT; f.reverse = 0; f.hsStride = 1024;
        r.xp = xpB; r.U = l ? eU1b : eU0b; r.h_init = zero; r.c_init = zero;
        r.hb0 = hbuf + 32768; r.hb1 = hbuf + 49152;
        r.hs = hs + 512; r.hT = hT + 512; r.cT = cT + 512; r.reverse = 1; r.hsStride = 1024;
        scan_kernel<<<256, 256, SMEM_SCAN>>>(f, r, 2, bar + l);
    }

    // enc_out (N=512, K=1024)
    split_kernel<<<SPG(786432), 256>>>(enc2, pool + PB_ACTH, pool + PB_ACTL, 786432);
    gemm_mma_kernel<<<dim3(24, 4), 256, GEMM3_SMEM>>>(
        pool + PB_ACTH, pool + PB_ACTL, pool + PB_OWH, pool + PB_OWL,
        out_b, enco, 3072, 512, 1024);

    // bridge: 4 jobs merged into one launch
    {
        B4 j0 = {g + OFF_HT, hpW, hpb, g + OFF_DH0};
        B4 j1 = {g + OFF_CT, cpW, cpb, g + OFF_DC0};
        B4 j2 = {g + OFF_HT + 32768u, hpW + 524288u, hpb + 512, g + OFF_DH0 + 16384u};
        B4 j3 = {g + OFF_CT + 32768u, cpW + 524288u, cpb + 512, g + OFF_DC0 + 16384u};
        bridge_kernel<<<dim3(4, 4), 256>>>(j0, j1, j2, j3);
    }

    // ---------------- decoder ----------------
    for (int l = 0; l < 2; l++) {
        const __nv_bfloat16 *xh, *xl;
        int K;
        if (l == 0) { xh = pool + PB_EMBTH; xl = pool + PB_EMBTL; K = 256; }
        else {
            split_kernel<<<SPG(393216), 256>>>(dec0, pool + PB_ACTH, pool + PB_ACTL, 393216);
            xh = pool + PB_ACTH; xl = pool + PB_ACTL; K = 512;
        }
        gemm_mma_kernel<<<dim3(24, 16), 256, GEMM3_SMEM>>>(
            xh, xl, l ? pool + PB_DW1H : pool + PB_DW0H,
            l ? pool + PB_DW1L : pool + PB_DW0L, l ? db1 : db0, xpA, 3072, 2048, K);
        ScanArgs a;
        a.xp = xpA; a.U = l ? dU1 : dU0;
        a.h_init = g + OFF_DH0 + (size_t)l * 16384u;
        a.c_init = g + OFF_DC0 + (size_t)l * 16384u;
        a.hb0 = hbuf; a.hb1 = hbuf + 16384;
        a.hs = l ? comb : dec0; a.hT = dscr; a.cT = dscr + 32768;
        a.reverse = 0; a.hsStride = l ? 1024 : 512;
        scan_kernel<<<128, 256, SMEM_SCAN>>>(a, a, 1, bar + 2 + l);
    }

    // attention -> comb[:,512:]
    attention_kernel<<<dim3(32, 12), 128, SMEM_ATT>>>(enco, src_seq, comb);

    // logits: fp16 A single-plane, fp16 B hi/lo (B pre-scaled by 512)
    split16_one_kernel<<<SPG(786432), 256>>>(comb, combA16, 786432);
    gemm_f16_kernel<<<dim3(24, 250), 256, GEMM2_SMEM>>>(
        combA16, fcWh16, fcWl16, fcb, out, 3072, NV, 1024, 1.0f / 512.0f);
}